// round 6
// baseline (speedup 1.0000x reference)
#include <cuda_runtime.h>
#include <math.h>
#include <stdint.h>

#define T_TOK     8192
#define DMODEL    1024
#define DFF       4096
#define E_ROUTED  7
#define TOPK      2
#define CAPACITY  2926
#define WPER      ((size_t)DMODEL * DFF)   // 4,194,304 elems per expert matrix

// ---------------- scratch ----------------
__device__ float g_ht[(size_t)T_TOK * DMODEL];   // tf32-rounded LN output (GEMM A)
__device__ int   g_topidx[T_TOK * TOPK];
__device__ float g_gate[T_TOK * TOPK];
__device__ int   g_pos[TOPK * T_TOK];
__device__ int   g_slot_token[E_ROUTED * CAPACITY];
__device__ int   g_count[E_ROUTED];
__device__ float g_w1r[8 * WPER];                // tf32-rounded weights; e=7 -> shared
__device__ float g_w3r[8 * WPER];
__device__ float g_w2r[8 * WPER];
__device__ float g_ub [(size_t)E_ROUTED * CAPACITY * DFF];  // u = silu(a)*b, rounded
__device__ float g_ubs[(size_t)T_TOK * DFF];
__device__ float g_ye [(size_t)E_ROUTED * CAPACITY * DMODEL];
__device__ float g_ys [(size_t)T_TOK * DMODEL];

// ---------------- helpers ----------------
__device__ __forceinline__ uint32_t smem_u32(const void* p) {
    return (uint32_t)__cvta_generic_to_shared(p);
}
__device__ __forceinline__ float tf32r(float x) {
    uint32_t u;
    asm("cvt.rna.tf32.f32 %0, %1;" : "=r"(u) : "f"(x));
    return __uint_as_float(u);
}
__device__ __forceinline__ void cp16(uint32_t d, const float* s) {
    asm volatile("cp.async.cg.shared.global [%0], [%1], 16;" :: "r"(d), "l"(s) : "memory");
}
__device__ __forceinline__ void cp_commit() {
    asm volatile("cp.async.commit_group;" ::: "memory");
}
template <int N>
__device__ __forceinline__ void cp_wait() {
    asm volatile("cp.async.wait_group %0;" :: "n"(N) : "memory");
}
__device__ __forceinline__ void mma_tf32(float c[4], uint32_t a0, uint32_t a1,
                                         uint32_t a2, uint32_t a3,
                                         uint32_t b0, uint32_t b1) {
    asm volatile(
        "mma.sync.aligned.m16n8k8.row.col.f32.tf32.tf32.f32 "
        "{%0,%1,%2,%3},{%4,%5,%6,%7},{%8,%9},{%0,%1,%2,%3};"
        : "+f"(c[0]), "+f"(c[1]), "+f"(c[2]), "+f"(c[3])
        : "r"(a0), "r"(a1), "r"(a2), "r"(a3), "r"(b0), "r"(b1));
}
__device__ __forceinline__ float silu_f(float v) { return v / (1.0f + __expf(-v)); }

// ---------------- 0) Fused LayerNorm + Router ----------------
__device__ __forceinline__ float blockReduceSum256(float v, float* sh8) {
    int lane = threadIdx.x & 31, wid = threadIdx.x >> 5;
    #pragma unroll
    for (int o = 16; o; o >>= 1) v += __shfl_down_sync(0xffffffffu, v, o);
    if (lane == 0) sh8[wid] = v;
    __syncthreads();
    float r = (threadIdx.x < 8) ? sh8[threadIdx.x] : 0.0f;
    if (wid == 0) {
        #pragma unroll
        for (int o = 4; o; o >>= 1) r += __shfl_down_sync(0xffffffffu, r, o);
        if (lane == 0) sh8[0] = r;
    }
    __syncthreads();
    float res = sh8[0];
    __syncthreads();
    return res;
}

__global__ void ln_router_kernel(const float* __restrict__ x,
                                 const float* __restrict__ gamma,
                                 const float* __restrict__ beta,
                                 const float* __restrict__ Wr) {
    __shared__ float sh[8];
    __shared__ double shd[8][E_ROUTED];
    int t = blockIdx.x, d4 = threadIdx.x;
    int lane = threadIdx.x & 31, wid = threadIdx.x >> 5;
    float4 v = reinterpret_cast<const float4*>(x + (size_t)t * DMODEL)[d4];
    float mu = blockReduceSum256(v.x + v.y + v.z + v.w, sh) * (1.0f / DMODEL);
    float dx = v.x - mu, dy = v.y - mu, dz = v.z - mu, dw = v.w - mu;
    float var = blockReduceSum256(dx*dx + dy*dy + dz*dz + dw*dw, sh) * (1.0f / DMODEL);
    float inv = rsqrtf(var + 1e-5f);
    float4 gg = reinterpret_cast<const float4*>(gamma)[d4];
    float4 bb = reinterpret_cast<const float4*>(beta)[d4];
    float4 o;
    o.x = dx*inv*gg.x + bb.x; o.y = dy*inv*gg.y + bb.y;
    o.z = dz*inv*gg.z + bb.z; o.w = dw*inv*gg.w + bb.w;
    float4 r;
    r.x = tf32r(o.x); r.y = tf32r(o.y); r.z = tf32r(o.z); r.w = tf32r(o.w);
    reinterpret_cast<float4*>(g_ht + (size_t)t * DMODEL)[d4] = r;

    // router logits in fp64 over exact fp32 h
    const int d0 = d4 * 4;
    double acc[E_ROUTED];
    #pragma unroll
    for (int e = 0; e < E_ROUTED; e++) {
        acc[e] = (double)o.x * (double)Wr[(size_t)(d0+0)*E_ROUTED + e]
               + (double)o.y * (double)Wr[(size_t)(d0+1)*E_ROUTED + e]
               + (double)o.z * (double)Wr[(size_t)(d0+2)*E_ROUTED + e]
               + (double)o.w * (double)Wr[(size_t)(d0+3)*E_ROUTED + e];
    }
    #pragma unroll
    for (int e = 0; e < E_ROUTED; e++)
        #pragma unroll
        for (int off = 16; off; off >>= 1)
            acc[e] += __shfl_down_sync(0xffffffffu, acc[e], off);
    if (lane == 0)
        #pragma unroll
        for (int e = 0; e < E_ROUTED; e++) shd[wid][e] = acc[e];
    __syncthreads();
    if (threadIdx.x == 0) {
        float vv[E_ROUTED];
        #pragma unroll
        for (int e = 0; e < E_ROUTED; e++) {
            double s = 0.0;
            #pragma unroll
            for (int w = 0; w < 8; w++) s += shd[w][e];
            vv[e] = (float)s;
        }
        int i1 = 0;
        #pragma unroll
        for (int e = 1; e < E_ROUTED; e++) if (vv[e] > vv[i1]) i1 = e;
        int i2 = -1;
        #pragma unroll
        for (int e = 0; e < E_ROUTED; e++) {
            if (e == i1) continue;
            if (i2 < 0 || vv[e] > vv[i2]) i2 = e;
        }
        float m = vv[i1], e1 = expf(vv[i1]-m), e2 = expf(vv[i2]-m), invs = 1.0f/(e1+e2);
        g_topidx[t*2+0] = i1; g_topidx[t*2+1] = i2;
        g_gate[t*2+0] = e1*invs; g_gate[t*2+1] = e2*invs;
    }
}

// ---------------- 1) Pre-round weights to tf32 ----------------
__global__ void roundw_kernel(const float* __restrict__ W1, const float* __restrict__ W1s,
                              const float* __restrict__ W3, const float* __restrict__ W3s,
                              const float* __restrict__ W2, const float* __restrict__ W2s) {
    int z = blockIdx.z;
    const float* rsrc = (z == 0) ? W1 : (z == 1) ? W3 : W2;
    const float* ssrc = (z == 0) ? W1s : (z == 1) ? W3s : W2s;
    float* dst = (z == 0) ? g_w1r : (z == 1) ? g_w3r : g_w2r;
    size_t idx = ((size_t)blockIdx.x * 256 + threadIdx.x) * 4;   // elem index in [0, 8*WPER)
    int e = (int)(idx >> 22);                                     // WPER = 2^22
    size_t off = idx & (WPER - 1);
    const float* s = (e < E_ROUTED) ? rsrc + (size_t)e * WPER + off : ssrc + off;
    float4 v = *reinterpret_cast<const float4*>(s);
    float4 r;
    r.x = tf32r(v.x); r.y = tf32r(v.y); r.z = tf32r(v.z); r.w = tf32r(v.w);
    *reinterpret_cast<float4*>(dst + idx) = r;
}

// ---------------- 2) Dispatch positions ----------------
__global__ void pos_kernel() {
    int e = blockIdx.x;
    __shared__ int warpTot[8];
    int lane = threadIdx.x & 31, wid = threadIdx.x >> 5;
    int running = 0;
    for (int k = 0; k < TOPK; k++)
        for (int base = 0; base < T_TOK; base += 256) {
            int t = base + threadIdx.x;
            int match = (g_topidx[t*2+k] == e) ? 1 : 0;
            unsigned bal = __ballot_sync(0xffffffffu, match);
            int wpre = __popc(bal & ((1u << lane) - 1u));
            if (lane == 31) warpTot[wid] = wpre + match;
            __syncthreads();
            int wbase = 0;
            #pragma unroll
            for (int w = 0; w < 8; w++) if (w < wid) wbase += warpTot[w];
            if (match) {
                int p = running + wbase + wpre;
                if (p < CAPACITY) { g_pos[k*T_TOK+t] = p; g_slot_token[e*CAPACITY+p] = t; }
                else g_pos[k*T_TOK+t] = -1;
            }
            int tot = 0;
            #pragma unroll
            for (int w = 0; w < 8; w++) tot += warpTot[w];
            running += tot;
            __syncthreads();
        }
    if (threadIdx.x == 0) g_count[e] = (running < CAPACITY) ? running : CAPACITY;
}

// ================= 3) Fused W1+W3 tf32 mma.sync GEMM + SwiGLU =================
// BM=128, BN=64 (each of W1/W3), BK=32. Weights pre-rounded -> B frags are bare LDS.
#define LDA   36
#define LDB13 72
#define G13_SMEM ((2*128*LDA + 4*32*LDB13) * 4)   // 73728 B

__global__ void __launch_bounds__(256, 2) gemm13_mma() {
    extern __shared__ float sm[];
    float* sA  = sm;
    float* sB1 = sm + 2*128*LDA;
    float* sB3 = sB1 + 2*32*LDB13;
    const int e = blockIdx.z;
    const int n0 = blockIdx.x * 64;
    const int m0 = blockIdx.y * 128;
    const int cnt = (e < E_ROUTED) ? g_count[e] : T_TOK;
    if (m0 >= cnt) return;
    const int tid = threadIdx.x, wid = tid >> 5, lane = tid & 31;
    const int wm = wid >> 1, wn = wid & 1;
    const int gid = lane >> 2, t4 = lane & 3;

    const float* w1e = g_w1r + (size_t)e * WPER;
    const float* w3e = g_w3r + (size_t)e * WPER;

    const float* ag[4]; uint32_t aoff[4];
    #pragma unroll
    for (int i = 0; i < 4; i++) {
        int idx = tid + i*256;
        int r = idx >> 3, s = idx & 7;
        int mg = m0 + r;
        int tok = (e < E_ROUTED) ? ((mg < cnt) ? g_slot_token[e*CAPACITY + mg] : 0) : mg;
        ag[i] = g_ht + (size_t)tok * DMODEL + s*4;
        aoff[i] = (uint32_t)(r*LDA + s*4) * 4;
    }
    const float* b1g[2]; const float* b3g[2]; uint32_t boff[2];
    #pragma unroll
    for (int i = 0; i < 2; i++) {
        int idx = tid + i*256;
        int kr = idx >> 4, s = idx & 15;
        b1g[i] = w1e + (size_t)kr * DFF + n0 + s*4;
        b3g[i] = w3e + (size_t)kr * DFF + n0 + s*4;
        boff[i] = (uint32_t)(kr*LDB13 + s*4) * 4;
    }
    const uint32_t sAu  = smem_u32(sA);
    const uint32_t sB1u = smem_u32(sB1);
    const uint32_t sB3u = smem_u32(sB3);

    float c1[2][4][4] = {};
    float c3[2][4][4] = {};

    auto load_stage = [&](int s, int j) {
        uint32_t ao = sAu + (uint32_t)s*128*LDA*4;
        #pragma unroll
        for (int i = 0; i < 4; i++) cp16(ao + aoff[i], ag[i] + j*32);
        uint32_t b1o = sB1u + (uint32_t)s*32*LDB13*4;
        uint32_t b3o = sB3u + (uint32_t)s*32*LDB13*4;
        size_t roff = (size_t)j * 32 * DFF;
        #pragma unroll
        for (int i = 0; i < 2; i++) {
            cp16(b1o + boff[i], b1g[i] + roff);
            cp16(b3o + boff[i], b3g[i] + roff);
        }
        cp_commit();
    };
    auto compute = [&](int s) {
        const uint32_t* A  = (const uint32_t*)(sA + (s*128 + wm*32) * LDA);
        const uint32_t* B1 = (const uint32_t*)(sB1 + s*32*LDB13 + wn*32);
        const uint32_t* B3 = (const uint32_t*)(sB3 + s*32*LDB13 + wn*32);
        #pragma unroll
        for (int ks = 0; ks < 4; ks++) {
            const int kc = ks*8 + t4;
            uint32_t a[2][4];
            #pragma unroll
            for (int t = 0; t < 2; t++) {
                int r = t*16 + gid;
                a[t][0] = A[r*LDA + kc];
                a[t][1] = A[(r+8)*LDA + kc];
                a[t][2] = A[r*LDA + kc + 4];
                a[t][3] = A[(r+8)*LDA + kc + 4];
            }
            #pragma unroll
            for (int u = 0; u < 4; u++) {
                const int n = u*8 + gid;
                uint32_t p0 = B1[kc*LDB13 + n];
                uint32_t p1 = B1[(kc+4)*LDB13 + n];
                uint32_t q0 = B3[kc*LDB13 + n];
                uint32_t q1 = B3[(kc+4)*LDB13 + n];
                #pragma unroll
                for (int t = 0; t < 2; t++) {
                    mma_tf32(c1[t][u], a[t][0], a[t][1], a[t][2], a[t][3], p0, p1);
                    mma_tf32(c3[t][u], a[t][0], a[t][1], a[t][2], a[t][3], q0, q1);
                }
            }
        }
    };

    load_stage(0, 0);
    #pragma unroll 1
    for (int j = 0; j < DMODEL/32; ++j) {
        if (j + 1 < DMODEL/32) { load_stage((j+1) & 1, j+1); cp_wait<1>(); }
        else cp_wait<0>();
        __syncthreads();
        compute(j & 1);
        __syncthreads();
    }

    float* dstb = (e < E_ROUTED) ? g_ub + (size_t)e * CAPACITY * DFF : g_ubs;
    #pragma unroll
    for (int t = 0; t < 2; t++)
        #pragma unroll
        for (int half = 0; half < 2; half++) {
            int r = m0 + wm*32 + t*16 + gid + half*8;
            if (r < cnt) {
                float* drow = dstb + (size_t)r * DFF + n0 + wn*32 + t4*2;
                #pragma unroll
                for (int u = 0; u < 4; u++) {
                    int ci = half*2;
                    float2 o;
                    o.x = tf32r(silu_f(c1[t][u][ci])   * c3[t][u][ci]);
                    o.y = tf32r(silu_f(c1[t][u][ci+1]) * c3[t][u][ci+1]);
                    *reinterpret_cast<float2*>(drow + u*8) = o;
                }
            }
        }
}

// ================= 4) W2 tf32 mma.sync GEMM =================
#define LDB2 136
#define G2_SMEM ((2*128*LDA + 2*32*LDB2) * 4)   // 71680 B

__global__ void __launch_bounds__(256, 2) gemm2_mma() {
    extern __shared__ float sm[];
    float* sA = sm;
    float* sB = sm + 2*128*LDA;
    const int e = blockIdx.z;
    const int n0 = blockIdx.x * 128;
    const int m0 = blockIdx.y * 128;
    const int cnt = (e < E_ROUTED) ? g_count[e] : T_TOK;
    if (m0 >= cnt) return;
    const int tid = threadIdx.x, wid = tid >> 5, lane = tid & 31;
    const int wm = wid >> 1, wn = wid & 1;
    const int gid = lane >> 2, t4 = lane & 3;

    const float* Abase = (e < E_ROUTED) ? g_ub + (size_t)e * CAPACITY * DFF : g_ubs;
    const float* w2e = g_w2r + (size_t)e * WPER;

    const float* ag[4]; uint32_t aoff[4];
    #pragma unroll
    for (int i = 0; i < 4; i++) {
        int idx = tid + i*256;
        int r = idx >> 3, s = idx & 7;
        int mg = m0 + r;
        ag[i] = Abase + (size_t)((mg < cnt) ? mg : 0) * DFF + s*4;
        aoff[i] = (uint32_t)(r*LDA + s*4) * 4;
    }
    const float* bg[4]; uint32_t boff[4];
    #pragma unroll
    for (int i = 0; i < 4; i++) {
        int idx = tid + i*256;
        int kr = idx >> 5, s = idx & 31;
        bg[i] = w2e + (size_t)kr * DMODEL + n0 + s*4;
        boff[i] = (uint32_t)(kr*LDB2 + s*4) * 4;
    }
    const uint32_t sAu = smem_u32(sA);
    const uint32_t sBu = smem_u32(sB);

    float c[2][8][4] = {};

    auto load_stage = [&](int s, int j) {
        uint32_t ao = sAu + (uint32_t)s*128*LDA*4;
        uint32_t bo = sBu + (uint32_t)s*32*LDB2*4;
        size_t roff = (size_t)j * 32 * DMODEL;
        #pragma unroll
        for (int i = 0; i < 4; i++) {
            cp16(ao + aoff[i], ag[i] + j*32);
            cp16(bo + boff[i], bg[i] + roff);
        }
        cp_commit();
    };
    auto compute = [&](int s) {
        const uint32_t* A = (const uint32_t*)(sA + (s*128 + wm*32) * LDA);
        const uint32_t* B = (const uint32_t*)(sB + s*32*LDB2 + wn*64);
        #pragma unroll
        for (int ks = 0; ks < 4; ks++) {
            const int kc = ks*8 + t4;
            uint32_t a[2][4];
            #pragma unroll
            for (int t = 0; t < 2; t++) {
                int r = t*16 + gid;
                a[t][0] = A[r*LDA + kc];
                a[t][1] = A[(r+8)*LDA + kc];
                a[t][2] = A[r*LDA + kc + 4];
                a[t][3] = A[(r+8)*LDA + kc + 4];
            }
            #pragma unroll
            for (int u = 0; u < 8; u++) {
                const int n = u*8 + gid;
                uint32_t b0 = B[kc*LDB2 + n];
                uint32_t b1 = B[(kc+4)*LDB2 + n];
                #pragma unroll
                for (int t = 0; t < 2; t++)
                    mma_tf32(c[t][u], a[t][0], a[t][1], a[t][2], a[t][3], b0, b1);
            }
        }
    };

    load_stage(0, 0);
    #pragma unroll 1
    for (int j = 0; j < DFF/32; ++j) {
        if (j + 1 < DFF/32) { load_stage((j+1) & 1, j+1); cp_wait<1>(); }
        else cp_wait<0>();
        __syncthreads();
        compute(j & 1);
        __syncthreads();
    }

    float* dstb = (e < E_ROUTED) ? g_ye + (size_t)e * CAPACITY * DMODEL : g_ys;
    #pragma unroll
    for (int t = 0; t < 2; t++)
        #pragma unroll
        for (int half = 0; half < 2; half++) {
            int r = m0 + wm*32 + t*16 + gid + half*8;
            if (r < cnt) {
                float* drow = dstb + (size_t)r * DMODEL + n0 + wn*64 + t4*2;
                #pragma unroll
                for (int u = 0; u < 8; u++) {
                    int ci = half*2;
                    float2 o; o.x = c[t][u][ci]; o.y = c[t][u][ci+1];
                    *reinterpret_cast<float2*>(drow + u*8) = o;
                }
            }
        }
}

// ---------------- 5) Combine ----------------
__global__ void combine_kernel(float* __restrict__ out) {
    int t = blockIdx.x, d4 = threadIdx.x;
    float4 o = reinterpret_cast<const float4*>(g_ys + (size_t)t * DMODEL)[d4];
    #pragma unroll
    for (int k = 0; k < TOPK; k++) {
        int p = g_pos[k * T_TOK + t];
        if (p >= 0) {
            int e = g_topidx[t*2+k];
            float gv = g_gate[t*2+k];
            float4 y = reinterpret_cast<const float4*>(g_ye + ((size_t)e*CAPACITY + p) * DMODEL)[d4];
            o.x += gv*y.x; o.y += gv*y.y; o.z += gv*y.z; o.w += gv*y.w;
        }
    }
    reinterpret_cast<float4*>(out + (size_t)t * DMODEL)[d4] = o;
}

// ---------------- launch ----------------
extern "C" void kernel_launch(void* const* d_in, const int* in_sizes, int n_in,
                              void* d_out, int out_size) {
    (void)in_sizes; (void)n_in; (void)out_size;
    const float* x    = (const float*)d_in[0];
    const float* ln_g = (const float*)d_in[1];
    const float* ln_b = (const float*)d_in[2];
    const float* Wr   = (const float*)d_in[3];
    const float* W1   = (const float*)d_in[4];
    const float* W3   = (const float*)d_in[5];
    const float* W2   = (const float*)d_in[6];
    const float* W1s  = (const float*)d_in[7];
    const float* W3s  = (const float*)d_in[8];
    const float* W2s  = (const float*)d_in[9];
    float* out = (float*)d_out;

    cudaFuncSetAttribute(gemm13_mma, cudaFuncAttributeMaxDynamicSharedMemorySize, G13_SMEM);
    cudaFuncSetAttribute(gemm2_mma,  cudaFuncAttributeMaxDynamicSharedMemorySize, G2_SMEM);

    ln_router_kernel<<<T_TOK, 256>>>(x, ln_g, ln_b, Wr);                       // 0
    roundw_kernel<<<dim3(8 * WPER / 1024, 1, 3), 256>>>(W1, W1s, W3, W3s, W2, W2s); // 1
    pos_kernel<<<E_ROUTED, 256>>>();                                           // 2
    gemm13_mma<<<dim3(DFF/64, T_TOK/128, E_ROUTED + 1), 256, G13_SMEM>>>();    // 3 <- ncu slot
    gemm2_mma <<<dim3(DMODEL/128, T_TOK/128, E_ROUTED + 1), 256, G2_SMEM>>>(); // 4
    combine_kernel<<<T_TOK, 256>>>(out);                                       // 5
}

// round 8
// speedup vs baseline: 1.0260x; 1.0260x over previous
#include <cuda_runtime.h>
#include <math.h>
#include <stdint.h>

#define T_TOK     8192
#define DMODEL    1024
#define DFF       4096
#define E_ROUTED  7
#define TOPK      2
#define CAPACITY  2926

// ---------------- scratch ----------------
__device__ float g_ht[(size_t)T_TOK * DMODEL];   // tf32-rounded LN output (GEMM A)
__device__ int   g_topidx[T_TOK * TOPK];
__device__ float g_gate[T_TOK * TOPK];
__device__ int   g_pos[TOPK * T_TOK];
__device__ int   g_slot_token[E_ROUTED * CAPACITY];
__device__ int   g_count[E_ROUTED];
__device__ float g_ub [(size_t)E_ROUTED * CAPACITY * DFF];  // u = silu(a)*b, tf32-rounded
__device__ float g_ubs[(size_t)T_TOK * DFF];
__device__ float g_ye [(size_t)E_ROUTED * CAPACITY * DMODEL];
__device__ float g_ys [(size_t)T_TOK * DMODEL];

// ---------------- helpers ----------------
__device__ __forceinline__ uint32_t smem_u32(const void* p) {
    return (uint32_t)__cvta_generic_to_shared(p);
}
__device__ __forceinline__ float tf32r(float x) {
    uint32_t u;
    asm("cvt.rna.tf32.f32 %0, %1;" : "=r"(u) : "f"(x));
    return __uint_as_float(u);
}
__device__ __forceinline__ uint32_t tf32u(float x) {
    uint32_t u;
    asm("cvt.rna.tf32.f32 %0, %1;" : "=r"(u) : "f"(x));
    return u;
}
__device__ __forceinline__ void cp16(uint32_t d, const float* s) {
    asm volatile("cp.async.cg.shared.global [%0], [%1], 16;" :: "r"(d), "l"(s) : "memory");
}
__device__ __forceinline__ void cp_commit() {
    asm volatile("cp.async.commit_group;" ::: "memory");
}
template <int N>
__device__ __forceinline__ void cp_wait() {
    asm volatile("cp.async.wait_group %0;" :: "n"(N) : "memory");
}
__device__ __forceinline__ void mma_tf32(float c[4], uint32_t a0, uint32_t a1,
                                         uint32_t a2, uint32_t a3,
                                         uint32_t b0, uint32_t b1) {
    asm volatile(
        "mma.sync.aligned.m16n8k8.row.col.f32.tf32.tf32.f32 "
        "{%0,%1,%2,%3},{%4,%5,%6,%7},{%8,%9},{%0,%1,%2,%3};"
        : "+f"(c[0]), "+f"(c[1]), "+f"(c[2]), "+f"(c[3])
        : "r"(a0), "r"(a1), "r"(a2), "r"(a3), "r"(b0), "r"(b1));
}
__device__ __forceinline__ float silu_f(float v) { return v / (1.0f + __expf(-v)); }

// ---------------- 0) Fused LayerNorm + Router ----------------
__device__ __forceinline__ float blockReduceSum256(float v, float* sh8) {
    int lane = threadIdx.x & 31, wid = threadIdx.x >> 5;
    #pragma unroll
    for (int o = 16; o; o >>= 1) v += __shfl_down_sync(0xffffffffu, v, o);
    if (lane == 0) sh8[wid] = v;
    __syncthreads();
    float r = (threadIdx.x < 8) ? sh8[threadIdx.x] : 0.0f;
    if (wid == 0) {
        #pragma unroll
        for (int o = 4; o; o >>= 1) r += __shfl_down_sync(0xffffffffu, r, o);
        if (lane == 0) sh8[0] = r;
    }
    __syncthreads();
    float res = sh8[0];
    __syncthreads();
    return res;
}

__global__ void ln_router_kernel(const float* __restrict__ x,
                                 const float* __restrict__ gamma,
                                 const float* __restrict__ beta,
                                 const float* __restrict__ Wr) {
    __shared__ float sh[8];
    __shared__ double shd[8][E_ROUTED];
    int t = blockIdx.x, d4 = threadIdx.x;
    int lane = threadIdx.x & 31, wid = threadIdx.x >> 5;
    float4 v = reinterpret_cast<const float4*>(x + (size_t)t * DMODEL)[d4];
    float mu = blockReduceSum256(v.x + v.y + v.z + v.w, sh) * (1.0f / DMODEL);
    float dx = v.x - mu, dy = v.y - mu, dz = v.z - mu, dw = v.w - mu;
    float var = blockReduceSum256(dx*dx + dy*dy + dz*dz + dw*dw, sh) * (1.0f / DMODEL);
    float inv = rsqrtf(var + 1e-5f);
    float4 gg = reinterpret_cast<const float4*>(gamma)[d4];
    float4 bb = reinterpret_cast<const float4*>(beta)[d4];
    float4 o;
    o.x = dx*inv*gg.x + bb.x; o.y = dy*inv*gg.y + bb.y;
    o.z = dz*inv*gg.z + bb.z; o.w = dw*inv*gg.w + bb.w;
    float4 r;
    r.x = tf32r(o.x); r.y = tf32r(o.y); r.z = tf32r(o.z); r.w = tf32r(o.w);
    reinterpret_cast<float4*>(g_ht + (size_t)t * DMODEL)[d4] = r;

    const int d0 = d4 * 4;
    double acc[E_ROUTED];
    #pragma unroll
    for (int e = 0; e < E_ROUTED; e++) {
        acc[e] = (double)o.x * (double)Wr[(size_t)(d0+0)*E_ROUTED + e]
               + (double)o.y * (double)Wr[(size_t)(d0+1)*E_ROUTED + e]
               + (double)o.z * (double)Wr[(size_t)(d0+2)*E_ROUTED + e]
               + (double)o.w * (double)Wr[(size_t)(d0+3)*E_ROUTED + e];
    }
    #pragma unroll
    for (int e = 0; e < E_ROUTED; e++)
        #pragma unroll
        for (int off = 16; off; off >>= 1)
            acc[e] += __shfl_down_sync(0xffffffffu, acc[e], off);
    if (lane == 0)
        #pragma unroll
        for (int e = 0; e < E_ROUTED; e++) shd[wid][e] = acc[e];
    __syncthreads();
    if (threadIdx.x == 0) {
        float vv[E_ROUTED];
        #pragma unroll
        for (int e = 0; e < E_ROUTED; e++) {
            double s = 0.0;
            #pragma unroll
            for (int w = 0; w < 8; w++) s += shd[w][e];
            vv[e] = (float)s;
        }
        int i1 = 0;
        #pragma unroll
        for (int e = 1; e < E_ROUTED; e++) if (vv[e] > vv[i1]) i1 = e;
        int i2 = -1;
        #pragma unroll
        for (int e = 0; e < E_ROUTED; e++) {
            if (e == i1) continue;
            if (i2 < 0 || vv[e] > vv[i2]) i2 = e;
        }
        float m = vv[i1], e1 = expf(vv[i1]-m), e2 = expf(vv[i2]-m), invs = 1.0f/(e1+e2);
        g_topidx[t*2+0] = i1; g_topidx[t*2+1] = i2;
        g_gate[t*2+0] = e1*invs; g_gate[t*2+1] = e2*invs;
    }
}

// ---------------- 1) Dispatch positions ----------------
__global__ void pos_kernel() {
    int e = blockIdx.x;
    __shared__ int warpTot[8];
    int lane = threadIdx.x & 31, wid = threadIdx.x >> 5;
    int running = 0;
    for (int k = 0; k < TOPK; k++)
        for (int base = 0; base < T_TOK; base += 256) {
            int t = base + threadIdx.x;
            int match = (g_topidx[t*2+k] == e) ? 1 : 0;
            unsigned bal = __ballot_sync(0xffffffffu, match);
            int wpre = __popc(bal & ((1u << lane) - 1u));
            if (lane == 31) warpTot[wid] = wpre + match;
            __syncthreads();
            int wbase = 0;
            #pragma unroll
            for (int w = 0; w < 8; w++) if (w < wid) wbase += warpTot[w];
            if (match) {
                int p = running + wbase + wpre;
                if (p < CAPACITY) { g_pos[k*T_TOK+t] = p; g_slot_token[e*CAPACITY+p] = t; }
                else g_pos[k*T_TOK+t] = -1;
            }
            int tot = 0;
            #pragma unroll
            for (int w = 0; w < 8; w++) tot += warpTot[w];
            running += tot;
            __syncthreads();
        }
    if (threadIdx.x == 0) g_count[e] = (running < CAPACITY) ? running : CAPACITY;
}

// ================= 2) Fused W1+W3 tf32 mma.sync GEMM + SwiGLU =================
// BM=128, BN=64 each of W1/W3, BK=32. 3-stage cp.async ring, ONE barrier/iter.
// Tail: last iteration must wait_group<0> (its own group is the oldest in flight).
#define LDA   36
#define LDB13 72
#define G13_STG (128*LDA + 2*32*LDB13)             // floats per stage = 9216
#define G13_SMEM (3 * G13_STG * 4)                 // 110592 B

__global__ void __launch_bounds__(256, 2) gemm13_mma(
    const float* __restrict__ W1, const float* __restrict__ W3,
    const float* __restrict__ W1s, const float* __restrict__ W3s)
{
    extern __shared__ float sm[];
    const int e = blockIdx.z;
    const int n0 = blockIdx.x * 64;
    const int m0 = blockIdx.y * 128;
    const int cnt = (e < E_ROUTED) ? g_count[e] : T_TOK;
    if (m0 >= cnt) return;
    const int tid = threadIdx.x, wid = tid >> 5, lane = tid & 31;
    const int wm = wid >> 1, wn = wid & 1;
    const int gid = lane >> 2, t4 = lane & 3;

    const float* w1e = (e < E_ROUTED) ? W1 + (size_t)e * DMODEL * DFF : W1s;
    const float* w3e = (e < E_ROUTED) ? W3 + (size_t)e * DMODEL * DFF : W3s;

    const float* ag[4]; uint32_t aoff[4];
    #pragma unroll
    for (int i = 0; i < 4; i++) {
        int idx = tid + i*256;
        int r = idx >> 3, s = idx & 7;
        int mg = m0 + r;
        int tok = (e < E_ROUTED) ? ((mg < cnt) ? g_slot_token[e*CAPACITY + mg] : 0) : mg;
        ag[i] = g_ht + (size_t)tok * DMODEL + s*4;
        aoff[i] = (uint32_t)(r*LDA + s*4) * 4;
    }
    const float* b1g[2]; const float* b3g[2]; uint32_t boff[2];
    #pragma unroll
    for (int i = 0; i < 2; i++) {
        int idx = tid + i*256;
        int kr = idx >> 4, s = idx & 15;
        b1g[i] = w1e + (size_t)kr * DFF + n0 + s*4;
        b3g[i] = w3e + (size_t)kr * DFF + n0 + s*4;
        boff[i] = (uint32_t)(kr*LDB13 + s*4) * 4;
    }
    const uint32_t sAu  = smem_u32(sm);
    const uint32_t sB1u = sAu + 128*LDA*4;
    const uint32_t sB3u = sB1u + 32*LDB13*4;

    float c1[2][4][4] = {};
    float c3[2][4][4] = {};

    auto load_stage = [&](int s, int j) {
        uint32_t st = (uint32_t)s * G13_STG * 4;
        uint32_t ao = sAu + st;
        #pragma unroll
        for (int i = 0; i < 4; i++) cp16(ao + aoff[i], ag[i] + j*32);
        uint32_t b1o = sB1u + st, b3o = sB3u + st;
        size_t roff = (size_t)j * 32 * DFF;
        #pragma unroll
        for (int i = 0; i < 2; i++) {
            cp16(b1o + boff[i], b1g[i] + roff);
            cp16(b3o + boff[i], b3g[i] + roff);
        }
        cp_commit();
    };
    auto compute = [&](int s) {
        const float* stage = sm + s * G13_STG;
        const uint32_t* A  = (const uint32_t*)(stage + wm*32*LDA);
        const float*    B1 = stage + 128*LDA + wn*32;
        const float*    B3 = B1 + 32*LDB13;
        #pragma unroll
        for (int ks = 0; ks < 4; ks++) {
            const int kc = ks*8 + t4;
            uint32_t a[2][4];
            #pragma unroll
            for (int t = 0; t < 2; t++) {
                int r = t*16 + gid;
                a[t][0] = A[r*LDA + kc];
                a[t][1] = A[(r+8)*LDA + kc];
                a[t][2] = A[r*LDA + kc + 4];
                a[t][3] = A[(r+8)*LDA + kc + 4];
            }
            #pragma unroll
            for (int u = 0; u < 4; u++) {
                const int n = u*8 + gid;
                uint32_t p0 = tf32u(B1[kc*LDB13 + n]);
                uint32_t p1 = tf32u(B1[(kc+4)*LDB13 + n]);
                uint32_t q0 = tf32u(B3[kc*LDB13 + n]);
                uint32_t q1 = tf32u(B3[(kc+4)*LDB13 + n]);
                #pragma unroll
                for (int t = 0; t < 2; t++) {
                    mma_tf32(c1[t][u], a[t][0], a[t][1], a[t][2], a[t][3], p0, p1);
                    mma_tf32(c3[t][u], a[t][0], a[t][1], a[t][2], a[t][3], q0, q1);
                }
            }
        }
    };

    const int nch = DMODEL/32;   // 32
    load_stage(0, 0);
    load_stage(1, 1);
    int s = 0;
    #pragma unroll 1
    for (int j = 0; j < nch; ++j) {
        if (j < nch - 1) cp_wait<1>();   // next group may stay in flight
        else             cp_wait<0>();   // TAIL: our own group is the only one left
        __syncthreads();
        compute(s);
        if (j + 2 < nch) {
            int s2 = s + 2; if (s2 >= 3) s2 -= 3;
            load_stage(s2, j + 2);
        }
        if (++s == 3) s = 0;
    }

    float* dstb = (e < E_ROUTED) ? g_ub + (size_t)e * CAPACITY * DFF : g_ubs;
    #pragma unroll
    for (int t = 0; t < 2; t++)
        #pragma unroll
        for (int half = 0; half < 2; half++) {
            int r = m0 + wm*32 + t*16 + gid + half*8;
            if (r < cnt) {
                float* drow = dstb + (size_t)r * DFF + n0 + wn*32 + t4*2;
                #pragma unroll
                for (int u = 0; u < 4; u++) {
                    int ci = half*2;
                    float2 o;
                    o.x = tf32r(silu_f(c1[t][u][ci])   * c3[t][u][ci]);
                    o.y = tf32r(silu_f(c1[t][u][ci+1]) * c3[t][u][ci+1]);
                    *reinterpret_cast<float2*>(drow + u*8) = o;
                }
            }
        }
}

// ================= 3) W2 tf32 mma.sync GEMM =================
#define LDB2 136
#define G2_STG (128*LDA + 32*LDB2)                 // floats per stage = 8960
#define G2_SMEM (3 * G2_STG * 4)                   // 107520 B

__global__ void __launch_bounds__(256, 2) gemm2_mma(
    const float* __restrict__ W2, const float* __restrict__ W2s)
{
    extern __shared__ float sm[];
    const int e = blockIdx.z;
    const int n0 = blockIdx.x * 128;
    const int m0 = blockIdx.y * 128;
    const int cnt = (e < E_ROUTED) ? g_count[e] : T_TOK;
    if (m0 >= cnt) return;
    const int tid = threadIdx.x, wid = tid >> 5, lane = tid & 31;
    const int wm = wid >> 1, wn = wid & 1;
    const int gid = lane >> 2, t4 = lane & 3;

    const float* Abase = (e < E_ROUTED) ? g_ub + (size_t)e * CAPACITY * DFF : g_ubs;
    const float* w2e = (e < E_ROUTED) ? W2 + (size_t)e * DFF * DMODEL : W2s;

    const float* ag[4]; uint32_t aoff[4];
    #pragma unroll
    for (int i = 0; i < 4; i++) {
        int idx = tid + i*256;
        int r = idx >> 3, s = idx & 7;
        int mg = m0 + r;
        ag[i] = Abase + (size_t)((mg < cnt) ? mg : 0) * DFF + s*4;
        aoff[i] = (uint32_t)(r*LDA + s*4) * 4;
    }
    const float* bg[4]; uint32_t boff[4];
    #pragma unroll
    for (int i = 0; i < 4; i++) {
        int idx = tid + i*256;
        int kr = idx >> 5, s = idx & 31;
        bg[i] = w2e + (size_t)kr * DMODEL + n0 + s*4;
        boff[i] = (uint32_t)(kr*LDB2 + s*4) * 4;
    }
    const uint32_t sAu = smem_u32(sm);
    const uint32_t sBu = sAu + 128*LDA*4;

    float c[2][8][4] = {};

    auto load_stage = [&](int s, int j) {
        uint32_t st = (uint32_t)s * G2_STG * 4;
        uint32_t ao = sAu + st, bo = sBu + st;
        size_t roff = (size_t)j * 32 * DMODEL;
        #pragma unroll
        for (int i = 0; i < 4; i++) {
            cp16(ao + aoff[i], ag[i] + j*32);
            cp16(bo + boff[i], bg[i] + roff);
        }
        cp_commit();
    };
    auto compute = [&](int s) {
        const float* stage = sm + s * G2_STG;
        const uint32_t* A = (const uint32_t*)(stage + wm*32*LDA);
        const float*    B = stage + 128*LDA + wn*64;
        #pragma unroll
        for (int ks = 0; ks < 4; ks++) {
            const int kc = ks*8 + t4;
            uint32_t a[2][4];
            #pragma unroll
            for (int t = 0; t < 2; t++) {
                int r = t*16 + gid;
                a[t][0] = A[r*LDA + kc];
                a[t][1] = A[(r+8)*LDA + kc];
                a[t][2] = A[r*LDA + kc + 4];
                a[t][3] = A[(r+8)*LDA + kc + 4];
            }
            #pragma unroll
            for (int u = 0; u < 8; u++) {
                const int n = u*8 + gid;
                uint32_t b0 = tf32u(B[kc*LDB2 + n]);
                uint32_t b1 = tf32u(B[(kc+4)*LDB2 + n]);
                #pragma unroll
                for (int t = 0; t < 2; t++)
                    mma_tf32(c[t][u], a[t][0], a[t][1], a[t][2], a[t][3], b0, b1);
            }
        }
    };

    const int nch = DFF/32;   // 128
    load_stage(0, 0);
    load_stage(1, 1);
    int s = 0;
    #pragma unroll 1
    for (int j = 0; j < nch; ++j) {
        if (j < nch - 1) cp_wait<1>();
        else             cp_wait<0>();   // TAIL fix
        __syncthreads();
        compute(s);
        if (j + 2 < nch) {
            int s2 = s + 2; if (s2 >= 3) s2 -= 3;
            load_stage(s2, j + 2);
        }
        if (++s == 3) s = 0;
    }

    float* dstb = (e < E_ROUTED) ? g_ye + (size_t)e * CAPACITY * DMODEL : g_ys;
    #pragma unroll
    for (int t = 0; t < 2; t++)
        #pragma unroll
        for (int half = 0; half < 2; half++) {
            int r = m0 + wm*32 + t*16 + gid + half*8;
            if (r < cnt) {
                float* drow = dstb + (size_t)r * DMODEL + n0 + wn*64 + t4*2;
                #pragma unroll
                for (int u = 0; u < 8; u++) {
                    int ci = half*2;
                    float2 o; o.x = c[t][u][ci]; o.y = c[t][u][ci+1];
                    *reinterpret_cast<float2*>(drow + u*8) = o;
                }
            }
        }
}

// ---------------- 4) Combine ----------------
__global__ void combine_kernel(float* __restrict__ out) {
    int t = blockIdx.x, d4 = threadIdx.x;
    float4 o = reinterpret_cast<const float4*>(g_ys + (size_t)t * DMODEL)[d4];
    #pragma unroll
    for (int k = 0; k < TOPK; k++) {
        int p = g_pos[k * T_TOK + t];
        if (p >= 0) {
            int e = g_topidx[t*2+k];
            float gv = g_gate[t*2+k];
            float4 y = reinterpret_cast<const float4*>(g_ye + ((size_t)e*CAPACITY + p) * DMODEL)[d4];
            o.x += gv*y.x; o.y += gv*y.y; o.z += gv*y.z; o.w += gv*y.w;
        }
    }
    reinterpret_cast<float4*>(out + (size_t)t * DMODEL)[d4] = o;
}

// ---------------- launch ----------------
extern "C" void kernel_launch(void* const* d_in, const int* in_sizes, int n_in,
                              void* d_out, int out_size) {
    (void)in_sizes; (void)n_in; (void)out_size;
    const float* x    = (const float*)d_in[0];
    const float* ln_g = (const float*)d_in[1];
    const float* ln_b = (const float*)d_in[2];
    const float* Wr   = (const float*)d_in[3];
    const float* W1   = (const float*)d_in[4];
    const float* W3   = (const float*)d_in[5];
    const float* W2   = (const float*)d_in[6];
    const float* W1s  = (const float*)d_in[7];
    const float* W3s  = (const float*)d_in[8];
    const float* W2s  = (const float*)d_in[9];
    float* out = (float*)d_out;

    cudaFuncSetAttribute(gemm13_mma, cudaFuncAttributeMaxDynamicSharedMemorySize, G13_SMEM);
    cudaFuncSetAttribute(gemm2_mma,  cudaFuncAttributeMaxDynamicSharedMemorySize, G2_SMEM);

    ln_router_kernel<<<T_TOK, 256>>>(x, ln_g, ln_b, Wr);                       // 0
    pos_kernel<<<E_ROUTED, 256>>>();                                           // 1
    gemm13_mma<<<dim3(DFF/64, T_TOK/128, E_ROUTED + 1), 256, G13_SMEM>>>(W1, W3, W1s, W3s); // 2
    gemm2_mma <<<dim3(DMODEL/128, T_TOK/128, E_ROUTED + 1), 256, G2_SMEM>>>(W2, W2s);       // 3 <- ncu slot
    combine_kernel<<<T_TOK, 256>>>(out);                                       // 4
}

// round 9
// speedup vs baseline: 1.6131x; 1.5722x over previous
#include <cuda_runtime.h>
#include <cuda_fp16.h>
#include <math.h>
#include <stdint.h>

#define T_TOK     8192
#define DMODEL    1024
#define DFF       4096
#define E_ROUTED  7
#define TOPK      2
#define CAPACITY  2926
#define WPER      ((size_t)DMODEL * DFF)

// ---------------- scratch ----------------
__device__ __half g_ht[(size_t)T_TOK * DMODEL];          // fp16 LN output (GEMM A)
__device__ int    g_topidx[T_TOK * TOPK];
__device__ float  g_gate[T_TOK * TOPK];
__device__ int    g_pos[TOPK * T_TOK];
__device__ int    g_slot_token[E_ROUTED * CAPACITY];
__device__ int    g_count[E_ROUTED];
__device__ __half g_w1t[8 * WPER];                       // [e][F][D] K-major fp16
__device__ __half g_w3t[8 * WPER];
__device__ __half g_w2t[8 * WPER];                       // [e][D][F] K-major fp16
__device__ __half g_ub [(size_t)E_ROUTED * CAPACITY * DFF];  // u = silu(a)*b fp16
__device__ __half g_ubs[(size_t)T_TOK * DFF];
__device__ float  g_ye [(size_t)E_ROUTED * CAPACITY * DMODEL];
__device__ float  g_ys [(size_t)T_TOK * DMODEL];

// ---------------- helpers ----------------
__device__ __forceinline__ uint32_t smem_u32(const void* p) {
    return (uint32_t)__cvta_generic_to_shared(p);
}
__device__ __forceinline__ void cp16(uint32_t d, const void* s) {
    asm volatile("cp.async.cg.shared.global [%0], [%1], 16;" :: "r"(d), "l"(s) : "memory");
}
__device__ __forceinline__ void cp_commit() {
    asm volatile("cp.async.commit_group;" ::: "memory");
}
template <int N>
__device__ __forceinline__ void cp_wait() {
    asm volatile("cp.async.wait_group %0;" :: "n"(N) : "memory");
}
__device__ __forceinline__ void mma_f16(float c[4], uint32_t a0, uint32_t a1,
                                        uint32_t a2, uint32_t a3,
                                        uint32_t b0, uint32_t b1) {
    asm volatile(
        "mma.sync.aligned.m16n8k16.row.col.f32.f16.f16.f32 "
        "{%0,%1,%2,%3},{%4,%5,%6,%7},{%8,%9},{%0,%1,%2,%3};"
        : "+f"(c[0]), "+f"(c[1]), "+f"(c[2]), "+f"(c[3])
        : "r"(a0), "r"(a1), "r"(a2), "r"(a3), "r"(b0), "r"(b1));
}
__device__ __forceinline__ float silu_f(float v) { return v / (1.0f + __expf(-v)); }

// ---------------- 0) Fused LayerNorm + Router ----------------
__device__ __forceinline__ float blockReduceSum256(float v, float* sh8) {
    int lane = threadIdx.x & 31, wid = threadIdx.x >> 5;
    #pragma unroll
    for (int o = 16; o; o >>= 1) v += __shfl_down_sync(0xffffffffu, v, o);
    if (lane == 0) sh8[wid] = v;
    __syncthreads();
    float r = (threadIdx.x < 8) ? sh8[threadIdx.x] : 0.0f;
    if (wid == 0) {
        #pragma unroll
        for (int o = 4; o; o >>= 1) r += __shfl_down_sync(0xffffffffu, r, o);
        if (lane == 0) sh8[0] = r;
    }
    __syncthreads();
    float res = sh8[0];
    __syncthreads();
    return res;
}

__global__ void ln_router_kernel(const float* __restrict__ x,
                                 const float* __restrict__ gamma,
                                 const float* __restrict__ beta,
                                 const float* __restrict__ Wr) {
    __shared__ float sh[8];
    __shared__ double shd[8][E_ROUTED];
    int t = blockIdx.x, d4 = threadIdx.x;
    int lane = threadIdx.x & 31, wid = threadIdx.x >> 5;
    float4 v = reinterpret_cast<const float4*>(x + (size_t)t * DMODEL)[d4];
    float mu = blockReduceSum256(v.x + v.y + v.z + v.w, sh) * (1.0f / DMODEL);
    float dx = v.x - mu, dy = v.y - mu, dz = v.z - mu, dw = v.w - mu;
    float var = blockReduceSum256(dx*dx + dy*dy + dz*dz + dw*dw, sh) * (1.0f / DMODEL);
    float inv = rsqrtf(var + 1e-5f);
    float4 gg = reinterpret_cast<const float4*>(gamma)[d4];
    float4 bb = reinterpret_cast<const float4*>(beta)[d4];
    float4 o;
    o.x = dx*inv*gg.x + bb.x; o.y = dy*inv*gg.y + bb.y;
    o.z = dz*inv*gg.z + bb.z; o.w = dw*inv*gg.w + bb.w;
    __half2* hrow = reinterpret_cast<__half2*>(g_ht + (size_t)t * DMODEL);
    hrow[d4*2+0] = __floats2half2_rn(o.x, o.y);
    hrow[d4*2+1] = __floats2half2_rn(o.z, o.w);

    const int d0 = d4 * 4;
    double acc[E_ROUTED];
    #pragma unroll
    for (int e = 0; e < E_ROUTED; e++) {
        acc[e] = (double)o.x * (double)Wr[(size_t)(d0+0)*E_ROUTED + e]
               + (double)o.y * (double)Wr[(size_t)(d0+1)*E_ROUTED + e]
               + (double)o.z * (double)Wr[(size_t)(d0+2)*E_ROUTED + e]
               + (double)o.w * (double)Wr[(size_t)(d0+3)*E_ROUTED + e];
    }
    #pragma unroll
    for (int e = 0; e < E_ROUTED; e++)
        #pragma unroll
        for (int off = 16; off; off >>= 1)
            acc[e] += __shfl_down_sync(0xffffffffu, acc[e], off);
    if (lane == 0)
        #pragma unroll
        for (int e = 0; e < E_ROUTED; e++) shd[wid][e] = acc[e];
    __syncthreads();
    if (threadIdx.x == 0) {
        float vv[E_ROUTED];
        #pragma unroll
        for (int e = 0; e < E_ROUTED; e++) {
            double s = 0.0;
            #pragma unroll
            for (int w = 0; w < 8; w++) s += shd[w][e];
            vv[e] = (float)s;
        }
        int i1 = 0;
        #pragma unroll
        for (int e = 1; e < E_ROUTED; e++) if (vv[e] > vv[i1]) i1 = e;
        int i2 = -1;
        #pragma unroll
        for (int e = 0; e < E_ROUTED; e++) {
            if (e == i1) continue;
            if (i2 < 0 || vv[e] > vv[i2]) i2 = e;
        }
        float m = vv[i1], e1 = expf(vv[i1]-m), e2 = expf(vv[i2]-m), invs = 1.0f/(e1+e2);
        g_topidx[t*2+0] = i1; g_topidx[t*2+1] = i2;
        g_gate[t*2+0] = e1*invs; g_gate[t*2+1] = e2*invs;
    }
}

// ---------------- 1) Transpose + fp16-convert ALL weights (one kernel) -----
// which = z>>3: 0->W1, 1->W3, 2->W2; e = z&7 (7 -> shared)
__global__ void transpose_all(const float* __restrict__ W1, const float* __restrict__ W1s,
                              const float* __restrict__ W3, const float* __restrict__ W3s,
                              const float* __restrict__ W2, const float* __restrict__ W2s) {
    __shared__ float t[32][33];
    int z = blockIdx.z, which = z >> 3, e = z & 7;
    int R = (which < 2) ? DMODEL : DFF;     // source rows (K)
    int C = (which < 2) ? DFF : DMODEL;     // source cols (N)
    const float* rsrc = (which == 0) ? W1 : (which == 1) ? W3 : W2;
    const float* ssrc = (which == 0) ? W1s : (which == 1) ? W3s : W2s;
    const float* s = (e < E_ROUTED) ? rsrc + (size_t)e * WPER : ssrc;
    __half* d = ((which == 0) ? g_w1t : (which == 1) ? g_w3t : g_w2t) + (size_t)e * WPER;
    int rt = (which < 2) ? blockIdx.y : blockIdx.x;   // R/32 tiles
    int ct = (which < 2) ? blockIdx.x : blockIdx.y;   // C/32 tiles
    int tx = threadIdx.x, ty = threadIdx.y;
    #pragma unroll
    for (int i = 0; i < 32; i += 8)
        t[ty+i][tx] = s[(size_t)(rt*32 + ty + i) * C + ct*32 + tx];
    __syncthreads();
    #pragma unroll
    for (int i = 0; i < 32; i += 8)
        d[(size_t)(ct*32 + ty + i) * R + rt*32 + tx] = __float2half(t[tx][ty+i]);
}

// ---------------- 2) Dispatch positions ----------------
__global__ void pos_kernel() {
    int e = blockIdx.x;
    __shared__ int warpTot[8];
    int lane = threadIdx.x & 31, wid = threadIdx.x >> 5;
    int running = 0;
    for (int k = 0; k < TOPK; k++)
        for (int base = 0; base < T_TOK; base += 256) {
            int t = base + threadIdx.x;
            int match = (g_topidx[t*2+k] == e) ? 1 : 0;
            unsigned bal = __ballot_sync(0xffffffffu, match);
            int wpre = __popc(bal & ((1u << lane) - 1u));
            if (lane == 31) warpTot[wid] = wpre + match;
            __syncthreads();
            int wbase = 0;
            #pragma unroll
            for (int w = 0; w < 8; w++) if (w < wid) wbase += warpTot[w];
            if (match) {
                int p = running + wbase + wpre;
                if (p < CAPACITY) { g_pos[k*T_TOK+t] = p; g_slot_token[e*CAPACITY+p] = t; }
                else g_pos[k*T_TOK+t] = -1;
            }
            int tot = 0;
            #pragma unroll
            for (int w = 0; w < 8; w++) tot += warpTot[w];
            running += tot;
            __syncthreads();
        }
    if (threadIdx.x == 0) g_count[e] = (running < CAPACITY) ? running : CAPACITY;
}

// ================= 3) Fused W1+W3 fp16 mma GEMM + SwiGLU =================
// BM=128, BN=64 each, BK=32. fp16 tiles, rows padded to 40 halfs (80B) ->
// conflict-free 32-bit fragment LDS. 4-stage cp.async ring, 1 barrier/iter.
#define LDH 40                           // halfs per row (row stride 80 B, 20 u32)
#define G13_A_B   (128*LDH*2)            // 10240 B
#define G13_B1_O  G13_A_B                // B1 at 10240
#define G13_B3_O  (G13_A_B + 64*LDH*2)   // B3 at 15360
#define G13_STGB  (G13_A_B + 2*64*LDH*2) // 20480 B
#define G13_SMEM  (4 * G13_STGB)         // 81920 B

__global__ void __launch_bounds__(256, 2) gemm13_mma() {
    extern __shared__ char smB[];
    const int e = blockIdx.z;
    const int n0 = blockIdx.x * 64;
    const int m0 = blockIdx.y * 128;
    const int cnt = (e < E_ROUTED) ? g_count[e] : T_TOK;
    if (m0 >= cnt) return;
    const int tid = threadIdx.x, wid = tid >> 5, lane = tid & 31;
    const int wm = wid >> 1, wn = wid & 1;
    const int gid = lane >> 2, t4 = lane & 3;

    const __half* w1e = g_w1t + (size_t)e * WPER;
    const __half* w3e = g_w3t + (size_t)e * WPER;

    // A: 128 rows x 4 chunks(16B) = 512 -> 2/thread
    const __half* agh[2]; uint32_t aoffB[2];
    #pragma unroll
    for (int i = 0; i < 2; i++) {
        int idx = tid + i*256;
        int r = idx >> 2, c = idx & 3;
        int mg = m0 + r;
        int tok = (e < E_ROUTED) ? ((mg < cnt) ? g_slot_token[e*CAPACITY + mg] : 0) : mg;
        agh[i] = g_ht + (size_t)tok * DMODEL + c*8;
        aoffB[i] = (uint32_t)(r*80 + c*16);
    }
    // B1/B3: 64 n-rows x 4 chunks = 256 -> 1/thread each
    const __half* b1gh; const __half* b3gh; uint32_t boffB;
    {
        int n = tid >> 2, c = tid & 3;
        b1gh = w1e + (size_t)(n0 + n) * DMODEL + c*8;
        b3gh = w3e + (size_t)(n0 + n) * DMODEL + c*8;
        boffB = (uint32_t)(n*80 + c*16);
    }
    const uint32_t sbase = smem_u32(smB);

    float c1[2][4][4] = {};
    float c3[2][4][4] = {};

    auto load_stage = [&](int s, int j) {
        uint32_t st = sbase + (uint32_t)s * G13_STGB;
        cp16(st + aoffB[0], agh[0] + j*32);
        cp16(st + aoffB[1], agh[1] + j*32);
        cp16(st + G13_B1_O + boffB, b1gh + j*32);
        cp16(st + G13_B3_O + boffB, b3gh + j*32);
        cp_commit();
    };
    auto compute = [&](int s) {
        const char* stage = smB + s * G13_STGB;
        const uint32_t* A  = (const uint32_t*)(stage) + (wm*32)*20;
        const uint32_t* B1 = (const uint32_t*)(stage + G13_B1_O) + (wn*32)*20;
        const uint32_t* B3 = (const uint32_t*)(stage + G13_B3_O) + (wn*32)*20;
        #pragma unroll
        for (int ks = 0; ks < 2; ks++) {
            const int kb = ks*8 + t4;
            uint32_t a[2][4];
            #pragma unroll
            for (int t = 0; t < 2; t++) {
                int r = t*16 + gid;
                a[t][0] = A[r*20 + kb];
                a[t][1] = A[(r+8)*20 + kb];
                a[t][2] = A[r*20 + kb + 4];
                a[t][3] = A[(r+8)*20 + kb + 4];
            }
            #pragma unroll
            for (int u = 0; u < 4; u++) {
                const int nr = (u*8 + gid)*20;
                uint32_t p0 = B1[nr + kb], p1 = B1[nr + kb + 4];
                uint32_t q0 = B3[nr + kb], q1 = B3[nr + kb + 4];
                #pragma unroll
                for (int t = 0; t < 2; t++) {
                    mma_f16(c1[t][u], a[t][0], a[t][1], a[t][2], a[t][3], p0, p1);
                    mma_f16(c3[t][u], a[t][0], a[t][1], a[t][2], a[t][3], q0, q1);
                }
            }
        }
    };

    const int nch = DMODEL/32;   // 32
    load_stage(0, 0); load_stage(1, 1); load_stage(2, 2);
    int s = 0;
    #pragma unroll 1
    for (int j = 0; j < nch; ++j) {
        if (j < nch - 2)      cp_wait<2>();
        else if (j == nch-2)  cp_wait<1>();
        else                  cp_wait<0>();
        __syncthreads();
        compute(s);
        if (j + 3 < nch) {
            int s2 = s + 3; if (s2 >= 4) s2 -= 4;
            load_stage(s2, j + 3);
        }
        if (++s == 4) s = 0;
    }

    __half* dstb = (e < E_ROUTED) ? g_ub + (size_t)e * CAPACITY * DFF : g_ubs;
    #pragma unroll
    for (int t = 0; t < 2; t++)
        #pragma unroll
        for (int half = 0; half < 2; half++) {
            int r = m0 + wm*32 + t*16 + gid + half*8;
            if (r < cnt) {
                __half* drow = dstb + (size_t)r * DFF + n0 + wn*32 + t4*2;
                #pragma unroll
                for (int u = 0; u < 4; u++) {
                    int ci = half*2;
                    float ux = silu_f(c1[t][u][ci])   * c3[t][u][ci];
                    float uy = silu_f(c1[t][u][ci+1]) * c3[t][u][ci+1];
                    *reinterpret_cast<__half2*>(drow + u*8) = __floats2half2_rn(ux, uy);
                }
            }
        }
}

// ================= 4) W2 fp16 mma GEMM =================
#define G2_A_B  (128*LDH*2)              // 10240 B
#define G2_B_O  G2_A_B
#define G2_STGB (2 * G2_A_B)             // 20480 B
#define G2_SMEM (4 * G2_STGB)            // 81920 B

__global__ void __launch_bounds__(256, 2) gemm2_mma() {
    extern __shared__ char smB[];
    const int e = blockIdx.z;
    const int n0 = blockIdx.x * 128;
    const int m0 = blockIdx.y * 128;
    const int cnt = (e < E_ROUTED) ? g_count[e] : T_TOK;
    if (m0 >= cnt) return;
    const int tid = threadIdx.x, wid = tid >> 5, lane = tid & 31;
    const int wm = wid >> 1, wn = wid & 1;
    const int gid = lane >> 2, t4 = lane & 3;

    const __half* Abase = (e < E_ROUTED) ? g_ub + (size_t)e * CAPACITY * DFF : g_ubs;
    const __half* w2e = g_w2t + (size_t)e * WPER;

    const __half* agh[2]; uint32_t aoffB[2];
    #pragma unroll
    for (int i = 0; i < 2; i++) {
        int idx = tid + i*256;
        int r = idx >> 2, c = idx & 3;
        int mg = m0 + r;
        agh[i] = Abase + (size_t)((mg < cnt) ? mg : 0) * DFF + c*8;
        aoffB[i] = (uint32_t)(r*80 + c*16);
    }
    const __half* bgh[2]; uint32_t boffB[2];
    #pragma unroll
    for (int i = 0; i < 2; i++) {
        int idx = tid + i*256;
        int n = idx >> 2, c = idx & 3;
        bgh[i] = w2e + (size_t)(n0 + n) * DFF + c*8;
        boffB[i] = (uint32_t)(n*80 + c*16);
    }
    const uint32_t sbase = smem_u32(smB);

    float cc[2][8][4] = {};

    auto load_stage = [&](int s, int j) {
        uint32_t st = sbase + (uint32_t)s * G2_STGB;
        cp16(st + aoffB[0], agh[0] + j*32);
        cp16(st + aoffB[1], agh[1] + j*32);
        cp16(st + G2_B_O + boffB[0], bgh[0] + j*32);
        cp16(st + G2_B_O + boffB[1], bgh[1] + j*32);
        cp_commit();
    };
    auto compute = [&](int s) {
        const char* stage = smB + s * G2_STGB;
        const uint32_t* A = (const uint32_t*)(stage) + (wm*32)*20;
        const uint32_t* B = (const uint32_t*)(stage + G2_B_O) + (wn*64)*20;
        #pragma unroll
        for (int ks = 0; ks < 2; ks++) {
            const int kb = ks*8 + t4;
            uint32_t a[2][4];
            #pragma unroll
            for (int t = 0; t < 2; t++) {
                int r = t*16 + gid;
                a[t][0] = A[r*20 + kb];
                a[t][1] = A[(r+8)*20 + kb];
                a[t][2] = A[r*20 + kb + 4];
                a[t][3] = A[(r+8)*20 + kb + 4];
            }
            #pragma unroll
            for (int u = 0; u < 8; u++) {
                const int nr = (u*8 + gid)*20;
                uint32_t b0 = B[nr + kb], b1 = B[nr + kb + 4];
                #pragma unroll
                for (int t = 0; t < 2; t++)
                    mma_f16(cc[t][u], a[t][0], a[t][1], a[t][2], a[t][3], b0, b1);
            }
        }
    };

    const int nch = DFF/32;   // 128
    load_stage(0, 0); load_stage(1, 1); load_stage(2, 2);
    int s = 0;
    #pragma unroll 1
    for (int j = 0; j < nch; ++j) {
        if (j < nch - 2)      cp_wait<2>();
        else if (j == nch-2)  cp_wait<1>();
        else                  cp_wait<0>();
        __syncthreads();
        compute(s);
        if (j + 3 < nch) {
            int s2 = s + 3; if (s2 >= 4) s2 -= 4;
            load_stage(s2, j + 3);
        }
        if (++s == 4) s = 0;
    }

    float* dstb = (e < E_ROUTED) ? g_ye + (size_t)e * CAPACITY * DMODEL : g_ys;
    #pragma unroll
    for (int t = 0; t < 2; t++)
        #pragma unroll
        for (int half = 0; half < 2; half++) {
            int r = m0 + wm*32 + t*16 + gid + half*8;
            if (r < cnt) {
                float* drow = dstb + (size_t)r * DMODEL + n0 + wn*64 + t4*2;
                #pragma unroll
                for (int u = 0; u < 8; u++) {
                    int ci = half*2;
                    float2 o; o.x = cc[t][u][ci]; o.y = cc[t][u][ci+1];
                    *reinterpret_cast<float2*>(drow + u*8) = o;
                }
            }
        }
}

// ---------------- 5) Combine ----------------
__global__ void combine_kernel(float* __restrict__ out) {
    int t = blockIdx.x, d4 = threadIdx.x;
    float4 o = reinterpret_cast<const float4*>(g_ys + (size_t)t * DMODEL)[d4];
    #pragma unroll
    for (int k = 0; k < TOPK; k++) {
        int p = g_pos[k * T_TOK + t];
        if (p >= 0) {
            int e = g_topidx[t*2+k];
            float gv = g_gate[t*2+k];
            float4 y = reinterpret_cast<const float4*>(g_ye + ((size_t)e*CAPACITY + p) * DMODEL)[d4];
            o.x += gv*y.x; o.y += gv*y.y; o.z += gv*y.z; o.w += gv*y.w;
        }
    }
    reinterpret_cast<float4*>(out + (size_t)t * DMODEL)[d4] = o;
}

// ---------------- launch ----------------
extern "C" void kernel_launch(void* const* d_in, const int* in_sizes, int n_in,
                              void* d_out, int out_size) {
    (void)in_sizes; (void)n_in; (void)out_size;
    const float* x    = (const float*)d_in[0];
    const float* ln_g = (const float*)d_in[1];
    const float* ln_b = (const float*)d_in[2];
    const float* Wr   = (const float*)d_in[3];
    const float* W1   = (const float*)d_in[4];
    const float* W3   = (const float*)d_in[5];
    const float* W2   = (const float*)d_in[6];
    const float* W1s  = (const float*)d_in[7];
    const float* W3s  = (const float*)d_in[8];
    const float* W2s  = (const float*)d_in[9];
    float* out = (float*)d_out;

    cudaFuncSetAttribute(gemm13_mma, cudaFuncAttributeMaxDynamicSharedMemorySize, G13_SMEM);
    cudaFuncSetAttribute(gemm2_mma,  cudaFuncAttributeMaxDynamicSharedMemorySize, G2_SMEM);

    ln_router_kernel<<<T_TOK, 256>>>(x, ln_g, ln_b, Wr);                        // 0
    transpose_all<<<dim3(128, 32, 24), dim3(32, 8)>>>(W1, W1s, W3, W3s, W2, W2s); // 1
    pos_kernel<<<E_ROUTED, 256>>>();                                            // 2
    gemm13_mma<<<dim3(DFF/64, T_TOK/128, E_ROUTED + 1), 256, G13_SMEM>>>();     // 3 <- ncu slot
    gemm2_mma <<<dim3(DMODEL/128, T_TOK/128, E_ROUTED + 1), 256, G2_SMEM>>>();  // 4
    combine_kernel<<<T_TOK, 256>>>(out);                                        // 5
}

// round 10
// speedup vs baseline: 1.6380x; 1.0154x over previous
#include <cuda_runtime.h>
#include <cuda_fp16.h>
#include <math.h>
#include <stdint.h>

#define T_TOK     8192
#define DMODEL    1024
#define DFF       4096
#define E_ROUTED  7
#define TOPK      2
#define CAPACITY  2926
#define WPER      ((size_t)DMODEL * DFF)

// ---------------- scratch ----------------
__device__ __half g_ht[(size_t)T_TOK * DMODEL];          // fp16 LN output (GEMM A)
__device__ int    g_topidx[T_TOK * TOPK];
__device__ float  g_gate[T_TOK * TOPK];
__device__ int    g_pos[TOPK * T_TOK];
__device__ int    g_slot_token[E_ROUTED * CAPACITY];
__device__ int    g_count[E_ROUTED];
__device__ __half g_w1t[8 * WPER];                       // [e][F][D] K-major fp16
__device__ __half g_w3t[8 * WPER];
__device__ __half g_w2t[8 * WPER];                       // [e][D][F] K-major fp16
__device__ __half g_ub [(size_t)E_ROUTED * CAPACITY * DFF];  // u = silu(a)*b fp16
__device__ __half g_ubs[(size_t)T_TOK * DFF];
__device__ float  g_ye [(size_t)E_ROUTED * CAPACITY * DMODEL];
__device__ float  g_ys [(size_t)T_TOK * DMODEL];

// ---------------- helpers ----------------
__device__ __forceinline__ uint32_t smem_u32(const void* p) {
    return (uint32_t)__cvta_generic_to_shared(p);
}
__device__ __forceinline__ void cp16(uint32_t d, const void* s) {
    asm volatile("cp.async.cg.shared.global [%0], [%1], 16;" :: "r"(d), "l"(s) : "memory");
}
__device__ __forceinline__ void cp_commit() {
    asm volatile("cp.async.commit_group;" ::: "memory");
}
template <int N>
__device__ __forceinline__ void cp_wait() {
    asm volatile("cp.async.wait_group %0;" :: "n"(N) : "memory");
}
__device__ __forceinline__ void mma_f16(float c[4], uint32_t a0, uint32_t a1,
                                        uint32_t a2, uint32_t a3,
                                        uint32_t b0, uint32_t b1) {
    asm volatile(
        "mma.sync.aligned.m16n8k16.row.col.f32.f16.f16.f32 "
        "{%0,%1,%2,%3},{%4,%5,%6,%7},{%8,%9},{%0,%1,%2,%3};"
        : "+f"(c[0]), "+f"(c[1]), "+f"(c[2]), "+f"(c[3])
        : "r"(a0), "r"(a1), "r"(a2), "r"(a3), "r"(b0), "r"(b1));
}
__device__ __forceinline__ float silu_f(float v) { return v / (1.0f + __expf(-v)); }

// ---------------- 0) Fused LayerNorm + Router ----------------
__device__ __forceinline__ float blockReduceSum256(float v, float* sh8) {
    int lane = threadIdx.x & 31, wid = threadIdx.x >> 5;
    #pragma unroll
    for (int o = 16; o; o >>= 1) v += __shfl_down_sync(0xffffffffu, v, o);
    if (lane == 0) sh8[wid] = v;
    __syncthreads();
    float r = (threadIdx.x < 8) ? sh8[threadIdx.x] : 0.0f;
    if (wid == 0) {
        #pragma unroll
        for (int o = 4; o; o >>= 1) r += __shfl_down_sync(0xffffffffu, r, o);
        if (lane == 0) sh8[0] = r;
    }
    __syncthreads();
    float res = sh8[0];
    __syncthreads();
    return res;
}

__global__ void ln_router_kernel(const float* __restrict__ x,
                                 const float* __restrict__ gamma,
                                 const float* __restrict__ beta,
                                 const float* __restrict__ Wr) {
    __shared__ float sh[8];
    __shared__ double shd[8][E_ROUTED];
    int t = blockIdx.x, d4 = threadIdx.x;
    int lane = threadIdx.x & 31, wid = threadIdx.x >> 5;
    float4 v = reinterpret_cast<const float4*>(x + (size_t)t * DMODEL)[d4];
    float mu = blockReduceSum256(v.x + v.y + v.z + v.w, sh) * (1.0f / DMODEL);
    float dx = v.x - mu, dy = v.y - mu, dz = v.z - mu, dw = v.w - mu;
    float var = blockReduceSum256(dx*dx + dy*dy + dz*dz + dw*dw, sh) * (1.0f / DMODEL);
    float inv = rsqrtf(var + 1e-5f);
    float4 gg = reinterpret_cast<const float4*>(gamma)[d4];
    float4 bb = reinterpret_cast<const float4*>(beta)[d4];
    float4 o;
    o.x = dx*inv*gg.x + bb.x; o.y = dy*inv*gg.y + bb.y;
    o.z = dz*inv*gg.z + bb.z; o.w = dw*inv*gg.w + bb.w;
    __half2* hrow = reinterpret_cast<__half2*>(g_ht + (size_t)t * DMODEL);
    hrow[d4*2+0] = __floats2half2_rn(o.x, o.y);
    hrow[d4*2+1] = __floats2half2_rn(o.z, o.w);

    const int d0 = d4 * 4;
    double acc[E_ROUTED];
    #pragma unroll
    for (int e = 0; e < E_ROUTED; e++) {
        acc[e] = (double)o.x * (double)Wr[(size_t)(d0+0)*E_ROUTED + e]
               + (double)o.y * (double)Wr[(size_t)(d0+1)*E_ROUTED + e]
               + (double)o.z * (double)Wr[(size_t)(d0+2)*E_ROUTED + e]
               + (double)o.w * (double)Wr[(size_t)(d0+3)*E_ROUTED + e];
    }
    #pragma unroll
    for (int e = 0; e < E_ROUTED; e++)
        #pragma unroll
        for (int off = 16; off; off >>= 1)
            acc[e] += __shfl_down_sync(0xffffffffu, acc[e], off);
    if (lane == 0)
        #pragma unroll
        for (int e = 0; e < E_ROUTED; e++) shd[wid][e] = acc[e];
    __syncthreads();
    if (threadIdx.x == 0) {
        float vv[E_ROUTED];
        #pragma unroll
        for (int e = 0; e < E_ROUTED; e++) {
            double s = 0.0;
            #pragma unroll
            for (int w = 0; w < 8; w++) s += shd[w][e];
            vv[e] = (float)s;
        }
        int i1 = 0;
        #pragma unroll
        for (int e = 1; e < E_ROUTED; e++) if (vv[e] > vv[i1]) i1 = e;
        int i2 = -1;
        #pragma unroll
        for (int e = 0; e < E_ROUTED; e++) {
            if (e == i1) continue;
            if (i2 < 0 || vv[e] > vv[i2]) i2 = e;
        }
        float m = vv[i1], e1 = expf(vv[i1]-m), e2 = expf(vv[i2]-m), invs = 1.0f/(e1+e2);
        g_topidx[t*2+0] = i1; g_topidx[t*2+1] = i2;
        g_gate[t*2+0] = e1*invs; g_gate[t*2+1] = e2*invs;
    }
}

// ---------------- 1) Transpose + fp16-convert ALL weights ----------------
__global__ void transpose_all(const float* __restrict__ W1, const float* __restrict__ W1s,
                              const float* __restrict__ W3, const float* __restrict__ W3s,
                              const float* __restrict__ W2, const float* __restrict__ W2s) {
    __shared__ float t[32][33];
    int z = blockIdx.z, which = z >> 3, e = z & 7;
    int R = (which < 2) ? DMODEL : DFF;
    int C = (which < 2) ? DFF : DMODEL;
    const float* rsrc = (which == 0) ? W1 : (which == 1) ? W3 : W2;
    const float* ssrc = (which == 0) ? W1s : (which == 1) ? W3s : W2s;
    const float* s = (e < E_ROUTED) ? rsrc + (size_t)e * WPER : ssrc;
    __half* d = ((which == 0) ? g_w1t : (which == 1) ? g_w3t : g_w2t) + (size_t)e * WPER;
    int rt = (which < 2) ? blockIdx.y : blockIdx.x;
    int ct = (which < 2) ? blockIdx.x : blockIdx.y;
    int tx = threadIdx.x, ty = threadIdx.y;
    #pragma unroll
    for (int i = 0; i < 32; i += 8)
        t[ty+i][tx] = s[(size_t)(rt*32 + ty + i) * C + ct*32 + tx];
    __syncthreads();
    #pragma unroll
    for (int i = 0; i < 32; i += 8)
        d[(size_t)(ct*32 + ty + i) * R + rt*32 + tx] = __float2half(t[tx][ty+i]);
}

// ---------------- 2) Dispatch positions ----------------
__global__ void pos_kernel() {
    int e = blockIdx.x;
    __shared__ int warpTot[8];
    int lane = threadIdx.x & 31, wid = threadIdx.x >> 5;
    int running = 0;
    for (int k = 0; k < TOPK; k++)
        for (int base = 0; base < T_TOK; base += 256) {
            int t = base + threadIdx.x;
            int match = (g_topidx[t*2+k] == e) ? 1 : 0;
            unsigned bal = __ballot_sync(0xffffffffu, match);
            int wpre = __popc(bal & ((1u << lane) - 1u));
            if (lane == 31) warpTot[wid] = wpre + match;
            __syncthreads();
            int wbase = 0;
            #pragma unroll
            for (int w = 0; w < 8; w++) if (w < wid) wbase += warpTot[w];
            if (match) {
                int p = running + wbase + wpre;
                if (p < CAPACITY) { g_pos[k*T_TOK+t] = p; g_slot_token[e*CAPACITY+p] = t; }
                else g_pos[k*T_TOK+t] = -1;
            }
            int tot = 0;
            #pragma unroll
            for (int w = 0; w < 8; w++) tot += warpTot[w];
            running += tot;
            __syncthreads();
        }
    if (threadIdx.x == 0) g_count[e] = (running < CAPACITY) ? running : CAPACITY;
}

// ================= 3) Fused W1+W3 fp16 mma GEMM + SwiGLU =================
// BM=128, BN=64 each, BK=32. 5-stage cp.async ring, ONE barrier per TWO chunks.
// Safety: at pair-j barrier all warps finished compute(j-1); loads target stages
// (j+3)%5=(j-2)%5 and (j+4)%5=(j-1)%5, both retired before this barrier.
#define LDH 40                           // halfs per row (80 B, 20 u32)
#define G13_A_B   (128*LDH*2)            // 10240 B
#define G13_B1_O  G13_A_B
#define G13_B3_O  (G13_A_B + 64*LDH*2)
#define G13_STGB  (G13_A_B + 2*64*LDH*2) // 20480 B
#define G13_SMEM  (5 * G13_STGB)         // 102400 B

__global__ void __launch_bounds__(256, 2) gemm13_mma() {
    extern __shared__ char smB[];
    const int e = blockIdx.z;
    const int n0 = blockIdx.x * 64;
    const int m0 = blockIdx.y * 128;
    const int cnt = (e < E_ROUTED) ? g_count[e] : T_TOK;
    if (m0 >= cnt) return;
    const int tid = threadIdx.x, wid = tid >> 5, lane = tid & 31;
    const int wm = wid >> 1, wn = wid & 1;
    const int gid = lane >> 2, t4 = lane & 3;

    const __half* w1e = g_w1t + (size_t)e * WPER;
    const __half* w3e = g_w3t + (size_t)e * WPER;

    const __half* agh[2]; uint32_t aoffB[2];
    #pragma unroll
    for (int i = 0; i < 2; i++) {
        int idx = tid + i*256;
        int r = idx >> 2, c = idx & 3;
        int mg = m0 + r;
        int tok = (e < E_ROUTED) ? ((mg < cnt) ? g_slot_token[e*CAPACITY + mg] : 0) : mg;
        agh[i] = g_ht + (size_t)tok * DMODEL + c*8;
        aoffB[i] = (uint32_t)(r*80 + c*16);
    }
    const __half* b1gh; const __half* b3gh; uint32_t boffB;
    {
        int n = tid >> 2, c = tid & 3;
        b1gh = w1e + (size_t)(n0 + n) * DMODEL + c*8;
        b3gh = w3e + (size_t)(n0 + n) * DMODEL + c*8;
        boffB = (uint32_t)(n*80 + c*16);
    }
    const uint32_t sbase = smem_u32(smB);

    float c1[2][4][4] = {};
    float c3[2][4][4] = {};

    auto load_stage = [&](int s, int j) {
        uint32_t st = sbase + (uint32_t)s * G13_STGB;
        cp16(st + aoffB[0], agh[0] + j*32);
        cp16(st + aoffB[1], agh[1] + j*32);
        cp16(st + G13_B1_O + boffB, b1gh + j*32);
        cp16(st + G13_B3_O + boffB, b3gh + j*32);
        cp_commit();
    };
    auto compute = [&](int s) {
        const char* stage = smB + s * G13_STGB;
        const uint32_t* A  = (const uint32_t*)(stage) + (wm*32)*20;
        const uint32_t* B1 = (const uint32_t*)(stage + G13_B1_O) + (wn*32)*20;
        const uint32_t* B3 = (const uint32_t*)(stage + G13_B3_O) + (wn*32)*20;
        #pragma unroll
        for (int ks = 0; ks < 2; ks++) {
            const int kb = ks*8 + t4;
            uint32_t a[2][4];
            #pragma unroll
            for (int t = 0; t < 2; t++) {
                int r = t*16 + gid;
                a[t][0] = A[r*20 + kb];
                a[t][1] = A[(r+8)*20 + kb];
                a[t][2] = A[r*20 + kb + 4];
                a[t][3] = A[(r+8)*20 + kb + 4];
            }
            #pragma unroll
            for (int u = 0; u < 4; u++) {
                const int nr = (u*8 + gid)*20;
                uint32_t p0 = B1[nr + kb], p1 = B1[nr + kb + 4];
                uint32_t q0 = B3[nr + kb], q1 = B3[nr + kb + 4];
                #pragma unroll
                for (int t = 0; t < 2; t++) {
                    mma_f16(c1[t][u], a[t][0], a[t][1], a[t][2], a[t][3], p0, p1);
                    mma_f16(c3[t][u], a[t][0], a[t][1], a[t][2], a[t][3], q0, q1);
                }
            }
        }
    };

    const int nch = DMODEL/32;   // 32 (even)
    load_stage(0, 0); load_stage(1, 1); load_stage(2, 2);
    int s = 0;
    #pragma unroll 1
    for (int j = 0; j < nch; j += 2) {
        if (j < nch - 2) cp_wait<1>();   // groups <= j+1 complete
        else             cp_wait<0>();   // TAIL pair
        __syncthreads();
        int s1 = s + 1; if (s1 >= 5) s1 -= 5;
        compute(s);
        compute(s1);
        if (j + 3 < nch) { int s3 = s + 3; if (s3 >= 5) s3 -= 5; load_stage(s3, j + 3); }
        if (j + 4 < nch) { int s4 = s + 4; if (s4 >= 5) s4 -= 5; load_stage(s4, j + 4); }
        s += 2; if (s >= 5) s -= 5;
    }

    __half* dstb = (e < E_ROUTED) ? g_ub + (size_t)e * CAPACITY * DFF : g_ubs;
    #pragma unroll
    for (int t = 0; t < 2; t++)
        #pragma unroll
        for (int half = 0; half < 2; half++) {
            int r = m0 + wm*32 + t*16 + gid + half*8;
            if (r < cnt) {
                __half* drow = dstb + (size_t)r * DFF + n0 + wn*32 + t4*2;
                #pragma unroll
                for (int u = 0; u < 4; u++) {
                    int ci = half*2;
                    float ux = silu_f(c1[t][u][ci])   * c3[t][u][ci];
                    float uy = silu_f(c1[t][u][ci+1]) * c3[t][u][ci+1];
                    *reinterpret_cast<__half2*>(drow + u*8) = __floats2half2_rn(ux, uy);
                }
            }
        }
}

// ================= 4) W2 fp16 mma GEMM =================
#define G2_A_B  (128*LDH*2)              // 10240 B
#define G2_B_O  G2_A_B
#define G2_STGB (2 * G2_A_B)             // 20480 B
#define G2_SMEM (5 * G2_STGB)            // 102400 B

__global__ void __launch_bounds__(256, 2) gemm2_mma() {
    extern __shared__ char smB[];
    const int e = blockIdx.z;
    const int n0 = blockIdx.x * 128;
    const int m0 = blockIdx.y * 128;
    const int cnt = (e < E_ROUTED) ? g_count[e] : T_TOK;
    if (m0 >= cnt) return;
    const int tid = threadIdx.x, wid = tid >> 5, lane = tid & 31;
    const int wm = wid >> 1, wn = wid & 1;
    const int gid = lane >> 2, t4 = lane & 3;

    const __half* Abase = (e < E_ROUTED) ? g_ub + (size_t)e * CAPACITY * DFF : g_ubs;
    const __half* w2e = g_w2t + (size_t)e * WPER;

    const __half* agh[2]; uint32_t aoffB[2];
    #pragma unroll
    for (int i = 0; i < 2; i++) {
        int idx = tid + i*256;
        int r = idx >> 2, c = idx & 3;
        int mg = m0 + r;
        agh[i] = Abase + (size_t)((mg < cnt) ? mg : 0) * DFF + c*8;
        aoffB[i] = (uint32_t)(r*80 + c*16);
    }
    const __half* bgh[2]; uint32_t boffB[2];
    #pragma unroll
    for (int i = 0; i < 2; i++) {
        int idx = tid + i*256;
        int n = idx >> 2, c = idx & 3;
        bgh[i] = w2e + (size_t)(n0 + n) * DFF + c*8;
        boffB[i] = (uint32_t)(n*80 + c*16);
    }
    const uint32_t sbase = smem_u32(smB);

    float cc[2][8][4] = {};

    auto load_stage = [&](int s, int j) {
        uint32_t st = sbase + (uint32_t)s * G2_STGB;
        cp16(st + aoffB[0], agh[0] + j*32);
        cp16(st + aoffB[1], agh[1] + j*32);
        cp16(st + G2_B_O + boffB[0], bgh[0] + j*32);
        cp16(st + G2_B_O + boffB[1], bgh[1] + j*32);
        cp_commit();
    };
    auto compute = [&](int s) {
        const char* stage = smB + s * G2_STGB;
        const uint32_t* A = (const uint32_t*)(stage) + (wm*32)*20;
        const uint32_t* B = (const uint32_t*)(stage + G2_B_O) + (wn*64)*20;
        #pragma unroll
        for (int ks = 0; ks < 2; ks++) {
            const int kb = ks*8 + t4;
            uint32_t a[2][4];
            #pragma unroll
            for (int t = 0; t < 2; t++) {
                int r = t*16 + gid;
                a[t][0] = A[r*20 + kb];
                a[t][1] = A[(r+8)*20 + kb];
                a[t][2] = A[r*20 + kb + 4];
                a[t][3] = A[(r+8)*20 + kb + 4];
            }
            #pragma unroll
            for (int u = 0; u < 8; u++) {
                const int nr = (u*8 + gid)*20;
                uint32_t b0 = B[nr + kb], b1 = B[nr + kb + 4];
                #pragma unroll
                for (int t = 0; t < 2; t++)
                    mma_f16(cc[t][u], a[t][0], a[t][1], a[t][2], a[t][3], b0, b1);
            }
        }
    };

    const int nch = DFF/32;   // 128 (even)
    load_stage(0, 0); load_stage(1, 1); load_stage(2, 2);
    int s = 0;
    #pragma unroll 1
    for (int j = 0; j < nch; j += 2) {
        if (j < nch - 2) cp_wait<1>();
        else             cp_wait<0>();   // TAIL pair
        __syncthreads();
        int s1 = s + 1; if (s1 >= 5) s1 -= 5;
        compute(s);
        compute(s1);
        if (j + 3 < nch) { int s3 = s + 3; if (s3 >= 5) s3 -= 5; load_stage(s3, j + 3); }
        if (j + 4 < nch) { int s4 = s + 4; if (s4 >= 5) s4 -= 5; load_stage(s4, j + 4); }
        s += 2; if (s >= 5) s -= 5;
    }

    float* dstb = (e < E_ROUTED) ? g_ye + (size_t)e * CAPACITY * DMODEL : g_ys;
    #pragma unroll
    for (int t = 0; t < 2; t++)
        #pragma unroll
        for (int half = 0; half < 2; half++) {
            int r = m0 + wm*32 + t*16 + gid + half*8;
            if (r < cnt) {
                float* drow = dstb + (size_t)r * DMODEL + n0 + wn*64 + t4*2;
                #pragma unroll
                for (int u = 0; u < 8; u++) {
                    int ci = half*2;
                    float2 o; o.x = cc[t][u][ci]; o.y = cc[t][u][ci+1];
                    *reinterpret_cast<float2*>(drow + u*8) = o;
                }
            }
        }
}

// ---------------- 5) Combine ----------------
__global__ void combine_kernel(float* __restrict__ out) {
    int t = blockIdx.x, d4 = threadIdx.x;
    float4 o = reinterpret_cast<const float4*>(g_ys + (size_t)t * DMODEL)[d4];
    #pragma unroll
    for (int k = 0; k < TOPK; k++) {
        int p = g_pos[k * T_TOK + t];
        if (p >= 0) {
            int e = g_topidx[t*2+k];
            float gv = g_gate[t*2+k];
            float4 y = reinterpret_cast<const float4*>(g_ye + ((size_t)e*CAPACITY + p) * DMODEL)[d4];
            o.x += gv*y.x; o.y += gv*y.y; o.z += gv*y.z; o.w += gv*y.w;
        }
    }
    reinterpret_cast<float4*>(out + (size_t)t * DMODEL)[d4] = o;
}

// ---------------- launch ----------------
extern "C" void kernel_launch(void* const* d_in, const int* in_sizes, int n_in,
                              void* d_out, int out_size) {
    (void)in_sizes; (void)n_in; (void)out_size;
    const float* x    = (const float*)d_in[0];
    const float* ln_g = (const float*)d_in[1];
    const float* ln_b = (const float*)d_in[2];
    const float* Wr   = (const float*)d_in[3];
    const float* W1   = (const float*)d_in[4];
    const float* W3   = (const float*)d_in[5];
    const float* W2   = (const float*)d_in[6];
    const float* W1s  = (const float*)d_in[7];
    const float* W3s  = (const float*)d_in[8];
    const float* W2s  = (const float*)d_in[9];
    float* out = (float*)d_out;

    cudaFuncSetAttribute(gemm13_mma, cudaFuncAttributeMaxDynamicSharedMemorySize, G13_SMEM);
    cudaFuncSetAttribute(gemm2_mma,  cudaFuncAttributeMaxDynamicSharedMemorySize, G2_SMEM);

    ln_router_kernel<<<T_TOK, 256>>>(x, ln_g, ln_b, Wr);                        // 0
    transpose_all<<<dim3(128, 32, 24), dim3(32, 8)>>>(W1, W1s, W3, W3s, W2, W2s); // 1
    pos_kernel<<<E_ROUTED, 256>>>();                                            // 2
    gemm13_mma<<<dim3(DFF/64, T_TOK/128, E_ROUTED + 1), 256, G13_SMEM>>>();     // 3 <- ncu slot
    gemm2_mma <<<dim3(DMODEL/128, T_TOK/128, E_ROUTED + 1), 256, G2_SMEM>>>();  // 4
    combine_kernel<<<T_TOK, 256>>>(out);                                        // 5
}